// round 14
// baseline (speedup 1.0000x reference)
#include <cuda_runtime.h>

// ODEFunc_5488968204447 — R12: R9 base + warp de-phasing: even warps run
// value-nets->mag-net, odd warps mag-net->value-nets, so MUFU-dense and
// FMA-dense phases coexist across a block's resident warps.

#define NPTS 2097152
#define TPB  128

typedef unsigned long long u64;

#define O_MW0 0
#define O_MB0 16
#define O_MW1 24
#define O_MB1 88
#define O_MW2 96
#define O_MB2 128
#define O_PW1 132
#define O_PB1 164
#define O_PW2 180
#define O_PB2 308
#define O_PW3 324
#define O_PB3 340
#define SM_N  344

__constant__ u64 cw2[SM_N];          // dup-packed: element i = (w[i], w[i])

__device__ __forceinline__ u64 pack2(float lo, float hi) {
    u64 r; asm("mov.b64 %0, {%1, %2};" : "=l"(r) : "f"(lo), "f"(hi)); return r;
}
__device__ __forceinline__ void unpack2(u64 v, float& lo, float& hi) {
    asm("mov.b64 {%0, %1}, %2;" : "=f"(lo), "=f"(hi) : "l"(v));
}
__device__ __forceinline__ u64 fma2(u64 a, u64 b, u64 c) {
    u64 d; asm("fma.rn.f32x2 %0, %1, %2, %3;" : "=l"(d) : "l"(a), "l"(b), "l"(c)); return d;
}
__device__ __forceinline__ u64 mul2(u64 a, u64 b) {
    u64 d; asm("mul.rn.f32x2 %0, %1, %2;" : "=l"(d) : "l"(a), "l"(b)); return d;
}
__device__ __forceinline__ float tanhfast(float x) {
    float y; asm("tanh.approx.f32 %0, %1;" : "=f"(y) : "f"(x)); return y;
}
__device__ __forceinline__ u64 tanh2(u64 a) {
    float lo, hi; unpack2(a, lo, hi);
    return pack2(tanhfast(lo), tanhfast(hi));
}
__device__ __forceinline__ u64 elu2(u64 a) {
    float lo, hi; unpack2(a, lo, hi);
    float elo = __expf(lo) - 1.0f, ehi = __expf(hi) - 1.0f;
    lo = lo > 0.0f ? lo : elo;
    hi = hi > 0.0f ? hi : ehi;
    return pack2(lo, hi);
}

// ---------------- prep: gather -> dup-packed blob written straight into the
// constant region through its symbol address ----------------
__global__ void prep_kernel(
    u64* __restrict__ dst,
    const float* __restrict__ mW0, const float* __restrict__ mb0,
    const float* __restrict__ mW1, const float* __restrict__ mb1,
    const float* __restrict__ mW2, const float* __restrict__ mb2,
    const float* __restrict__ pW1, const float* __restrict__ pb1,
    const float* __restrict__ pW2, const float* __restrict__ pb2,
    const float* __restrict__ pW3, const float* __restrict__ pb3)
{
    int i = threadIdx.x;
    if (i >= SM_N) return;
    float v;
    if      (i < O_MB0) v = mW0[i - O_MW0];
    else if (i < O_MW1) v = mb0[i - O_MB0];
    else if (i < O_MB1) v = mW1[i - O_MW1];
    else if (i < O_MW2) v = mb1[i - O_MB1];
    else if (i < O_MB2) v = mW2[i - O_MW2];
    else if (i < O_PW1) v = mb2[i - O_MB2];
    else if (i < O_PB1) v = pW1[i - O_PW1];
    else if (i < O_PW2) v = pb1[i - O_PB1];
    else if (i < O_PB2) v = pW2[i - O_PW2];
    else if (i < O_PW3) v = pb2[i - O_PB2];
    else if (i < O_PB3) v = pW3[i - O_PW3];
    else                v = pb3[i - O_PB3];
    dst[i] = pack2(v, v);
}

// ---- value nets (NV=2), fused fwd+bwd; returns g0,g1 (grad means * 0.5) ----
__device__ __forceinline__ void value_nets(const u64 X0, const u64 X1,
                                           u64& g0, u64& g1)
{
    g0 = pack2(0.0f, 0.0f);
    g1 = pack2(0.0f, 0.0f);
#pragma unroll
    for (int v = 0; v < 2; v++) {
        u64 f1[8];
#pragma unroll
        for (int o = 0; o < 8; o++) {
            u64 w0 = cw2[O_PW1 + v * 16 + 2 * o];
            u64 w1 = cw2[O_PW1 + v * 16 + 2 * o + 1];
            f1[o] = tanh2(fma2(w0, X0, fma2(w1, X1, cw2[O_PB1 + v * 8 + o])));
        }
        u64 z = cw2[O_PB3 + v];
        u64 gp[8];
#pragma unroll
        for (int p = 0; p < 8; p++) gp[p] = pack2(0.0f, 0.0f);
#pragma unroll
        for (int q = 0; q < 8; q++) {
            u64 acc = cw2[O_PB2 + v * 8 + q];
#pragma unroll
            for (int i = 0; i < 8; i++)
                acc = fma2(cw2[O_PW2 + v * 64 + 8 * q + i], f1[i], acc);
            u64 f2  = tanh2(acc);
            u64 w3q = cw2[O_PW3 + v * 8 + q];
            z = fma2(w3q, f2, z);
            u64 gq = mul2(w3q, fma2(f2, f2, pack2(-1.0f, -1.0f)));   // w3q*(f2^2-1)
#pragma unroll
            for (int p = 0; p < 8; p++)
                gp[p] = fma2(gq, cw2[O_PW2 + v * 64 + 8 * q + p], gp[p]);
        }
        // ss*0.5 via tanh identity: s(1-s) = 0.25*(1 - tanh^2(f3/2))
        float zl, zh; unpack2(z, zl, zh);
        float f3l = fmaf(0.5f, tanhfast(0.5f * zl), 0.5f);
        float f3h = fmaf(0.5f, tanhfast(0.5f * zh), 0.5f);
        float tl = tanhfast(0.5f * f3l);
        float th = tanhfast(0.5f * f3h);
        u64 ssp = pack2(fmaf(-0.125f * tl, tl, 0.125f),
                        fmaf(-0.125f * th, th, 0.125f));

        u64 gv0 = pack2(0.0f, 0.0f), gv1 = pack2(0.0f, 0.0f);
#pragma unroll
        for (int p = 0; p < 8; p++) {
            u64 tp = mul2(gp[p], fma2(f1[p], f1[p], pack2(-1.0f, -1.0f)));
            gv0 = fma2(tp, cw2[O_PW1 + v * 16 + 2 * p],     gv0);
            gv1 = fma2(tp, cw2[O_PW1 + v * 16 + 2 * p + 1], gv1);
        }
        g0 = fma2(gv0, ssp, g0);
        g1 = fma2(gv1, ssp, g1);
    }
}

// ---- magnitude net; returns m2, magA, magD ----
__device__ __forceinline__ void mag_net(const u64 X0, const u64 X1,
                                        u64& m2, u64& magA, u64& magD)
{
    u64 h[8];
#pragma unroll
    for (int o = 0; o < 8; o++) {
        u64 w0 = cw2[O_MW0 + 2 * o];
        u64 w1 = cw2[O_MW0 + 2 * o + 1];
        h[o] = elu2(fma2(w0, X0, fma2(w1, X1, cw2[O_MB0 + o])));
    }
    u64 h2[8];
#pragma unroll
    for (int o = 0; o < 8; o++) {
        u64 acc = cw2[O_MB1 + o];
#pragma unroll
        for (int i = 0; i < 8; i++)
            acc = fma2(cw2[O_MW1 + 8 * o + i], h[i], acc);
        h2[o] = elu2(acc);
    }
    u64 bv[4];
#pragma unroll
    for (int j = 0; j < 4; j++) {
        u64 acc = cw2[O_MB2 + j];
#pragma unroll
        for (int i = 0; i < 8; i++)
            acc = fma2(cw2[O_MW2 + 8 * j + i], h2[i], acc);
        bv[j] = acc;
    }
    m2   = fma2(bv[0], bv[1], mul2(bv[2], bv[3]));
    magA = fma2(bv[0], bv[0], mul2(bv[2], bv[2]));
    magD = fma2(bv[1], bv[1], mul2(bv[3], bv[3]));
}

// ---------------- main: 2 points per thread, warp-de-phased ----------------
__global__ __launch_bounds__(TPB, 6) void odefunc_kernel(
    const float* __restrict__ x, float* __restrict__ out)
{
    const int gid = blockIdx.x * TPB + threadIdx.x;
    float4 xv = reinterpret_cast<const float4*>(x)[gid];
    const u64 X0 = pack2(xv.x, xv.z);
    const u64 X1 = pack2(xv.y, xv.w);

    u64 g0, g1, m2, magA, magD;
    if ((threadIdx.x & 32) == 0) {
        // even warps: value nets (MUFU-heavy f1 first), then mag net
        value_nets(X0, X1, g0, g1);
        mag_net(X0, X1, m2, magA, magD);
    } else {
        // odd warps: mag net first, then value nets — opposite phase
        mag_net(X0, X1, m2, magA, magD);
        value_nets(X0, X1, g0, g1);
    }

    u64 o0 = fma2(magA, g0, mul2(m2, g1));
    u64 o1 = fma2(m2, g0, mul2(magD, g1));
    float o0l, o0h, o1l, o1h;
    unpack2(o0, o0l, o0h);
    unpack2(o1, o1l, o1h);
    reinterpret_cast<float4*>(out)[gid] = make_float4(o0l, o1l, o0h, o1h);
}

extern "C" void kernel_launch(void* const* d_in, const int* in_sizes, int n_in,
                              void* d_out, int out_size)
{
    const float* x   = (const float*)d_in[1];
    const float* mW0 = (const float*)d_in[2];
    const float* mb0 = (const float*)d_in[3];
    const float* mW1 = (const float*)d_in[4];
    const float* mb1 = (const float*)d_in[5];
    const float* mW2 = (const float*)d_in[6];
    const float* mb2 = (const float*)d_in[7];
    const float* pW1 = (const float*)d_in[8];
    const float* pb1 = (const float*)d_in[9];
    const float* pW2 = (const float*)d_in[10];
    const float* pb2 = (const float*)d_in[11];
    const float* pW3 = (const float*)d_in[12];
    const float* pb3 = (const float*)d_in[13];
    float* out = (float*)d_out;

    void* cw_ptr = nullptr;
    cudaGetSymbolAddress(&cw_ptr, cw2);

    prep_kernel<<<1, 352>>>((u64*)cw_ptr,
                            mW0, mb0, mW1, mb1, mW2, mb2,
                            pW1, pb1, pW2, pb2, pW3, pb3);

    const int nblocks = NPTS / 2 / TPB;   // 8192
    odefunc_kernel<<<nblocks, TPB>>>(x, out);
}

// round 15
// speedup vs baseline: 1.0042x; 1.0042x over previous
#include <cuda_runtime.h>

// ODEFunc_5488968204447 — R13: R9 base (best: 2 pts/thread, dup-packed constants,
// FFMA2, direct constant-region write) + every dot8 split into two parallel
// 4-deep accumulator chains merged by one packed add (halves chain latency).

#define NPTS 2097152
#define TPB  128

typedef unsigned long long u64;

#define O_MW0 0
#define O_MB0 16
#define O_MW1 24
#define O_MB1 88
#define O_MW2 96
#define O_MB2 128
#define O_PW1 132
#define O_PB1 164
#define O_PW2 180
#define O_PB2 308
#define O_PW3 324
#define O_PB3 340
#define SM_N  344

__constant__ u64 cw2[SM_N];          // dup-packed: element i = (w[i], w[i])

__device__ __forceinline__ u64 pack2(float lo, float hi) {
    u64 r; asm("mov.b64 %0, {%1, %2};" : "=l"(r) : "f"(lo), "f"(hi)); return r;
}
__device__ __forceinline__ void unpack2(u64 v, float& lo, float& hi) {
    asm("mov.b64 {%0, %1}, %2;" : "=f"(lo), "=f"(hi) : "l"(v));
}
__device__ __forceinline__ u64 fma2(u64 a, u64 b, u64 c) {
    u64 d; asm("fma.rn.f32x2 %0, %1, %2, %3;" : "=l"(d) : "l"(a), "l"(b), "l"(c)); return d;
}
__device__ __forceinline__ u64 mul2(u64 a, u64 b) {
    u64 d; asm("mul.rn.f32x2 %0, %1, %2;" : "=l"(d) : "l"(a), "l"(b)); return d;
}
__device__ __forceinline__ u64 add2(u64 a, u64 b) {
    u64 d; asm("add.rn.f32x2 %0, %1, %2;" : "=l"(d) : "l"(a), "l"(b)); return d;
}
__device__ __forceinline__ float tanhfast(float x) {
    float y; asm("tanh.approx.f32 %0, %1;" : "=f"(y) : "f"(x)); return y;
}
__device__ __forceinline__ u64 tanh2(u64 a) {
    float lo, hi; unpack2(a, lo, hi);
    return pack2(tanhfast(lo), tanhfast(hi));
}
__device__ __forceinline__ u64 elu2(u64 a) {
    float lo, hi; unpack2(a, lo, hi);
    float elo = __expf(lo) - 1.0f, ehi = __expf(hi) - 1.0f;
    lo = lo > 0.0f ? lo : elo;
    hi = hi > 0.0f ? hi : ehi;
    return pack2(lo, hi);
}
// dot over an 8-row of constants with vector a, as two parallel 4-chains.
// base is a compile-time constant index into cw2; bias folded into even chain.
__device__ __forceinline__ u64 dot8c(int base, const u64 a[8], u64 bias) {
    u64 e = fma2(cw2[base + 0], a[0], bias);
    u64 o = mul2(cw2[base + 1], a[1]);
    e = fma2(cw2[base + 2], a[2], e);
    o = fma2(cw2[base + 3], a[3], o);
    e = fma2(cw2[base + 4], a[4], e);
    o = fma2(cw2[base + 5], a[5], o);
    e = fma2(cw2[base + 6], a[6], e);
    o = fma2(cw2[base + 7], a[7], o);
    return add2(e, o);
}

// ---------------- prep: gather -> dup-packed blob written straight into the
// constant region through its symbol address ----------------
__global__ void prep_kernel(
    u64* __restrict__ dst,
    const float* __restrict__ mW0, const float* __restrict__ mb0,
    const float* __restrict__ mW1, const float* __restrict__ mb1,
    const float* __restrict__ mW2, const float* __restrict__ mb2,
    const float* __restrict__ pW1, const float* __restrict__ pb1,
    const float* __restrict__ pW2, const float* __restrict__ pb2,
    const float* __restrict__ pW3, const float* __restrict__ pb3)
{
    int i = threadIdx.x;
    if (i >= SM_N) return;
    float v;
    if      (i < O_MB0) v = mW0[i - O_MW0];
    else if (i < O_MW1) v = mb0[i - O_MB0];
    else if (i < O_MB1) v = mW1[i - O_MW1];
    else if (i < O_MW2) v = mb1[i - O_MB1];
    else if (i < O_MB2) v = mW2[i - O_MW2];
    else if (i < O_PW1) v = mb2[i - O_MB2];
    else if (i < O_PB1) v = pW1[i - O_PW1];
    else if (i < O_PW2) v = pb1[i - O_PB1];
    else if (i < O_PB2) v = pW2[i - O_PW2];
    else if (i < O_PW3) v = pb2[i - O_PB2];
    else if (i < O_PB3) v = pW3[i - O_PW3];
    else                v = pb3[i - O_PB3];
    dst[i] = pack2(v, v);
}

// ---------------- main: 2 points per thread ----------------
__global__ __launch_bounds__(TPB, 6) void odefunc_kernel(
    const float* __restrict__ x, float* __restrict__ out)
{
    const int gid = blockIdx.x * TPB + threadIdx.x;
    float4 xv = reinterpret_cast<const float4*>(x)[gid];
    const u64 X0 = pack2(xv.x, xv.z);
    const u64 X1 = pack2(xv.y, xv.w);

    // ---------------- value nets (NV=2), fused fwd+bwd ----------------
    u64 g0 = pack2(0.0f, 0.0f), g1 = pack2(0.0f, 0.0f);
#pragma unroll
    for (int v = 0; v < 2; v++) {
        u64 f1[8];
#pragma unroll
        for (int o = 0; o < 8; o++) {
            u64 w0 = cw2[O_PW1 + v * 16 + 2 * o];
            u64 w1 = cw2[O_PW1 + v * 16 + 2 * o + 1];
            f1[o] = tanh2(fma2(w0, X0, fma2(w1, X1, cw2[O_PB1 + v * 8 + o])));
        }
        u64 z = cw2[O_PB3 + v];
        u64 gp[8];
#pragma unroll
        for (int p = 0; p < 8; p++) gp[p] = pack2(0.0f, 0.0f);
#pragma unroll
        for (int q = 0; q < 8; q++) {
            u64 f2 = tanh2(dot8c(O_PW2 + v * 64 + 8 * q, f1, cw2[O_PB2 + v * 8 + q]));
            u64 w3q = cw2[O_PW3 + v * 8 + q];
            z = fma2(w3q, f2, z);
            u64 gq = mul2(w3q, fma2(f2, f2, pack2(-1.0f, -1.0f)));   // w3q*(f2^2-1)
#pragma unroll
            for (int p = 0; p < 8; p++)
                gp[p] = fma2(gq, cw2[O_PW2 + v * 64 + 8 * q + p], gp[p]);
        }
        // ss*0.5 via tanh identity: s(1-s) = 0.25*(1 - tanh^2(f3/2))
        float zl, zh; unpack2(z, zl, zh);
        float f3l = fmaf(0.5f, tanhfast(0.5f * zl), 0.5f);
        float f3h = fmaf(0.5f, tanhfast(0.5f * zh), 0.5f);
        float tl = tanhfast(0.5f * f3l);
        float th = tanhfast(0.5f * f3h);
        u64 ssp = pack2(fmaf(-0.125f * tl, tl, 0.125f),
                        fmaf(-0.125f * th, th, 0.125f));

        u64 gv0 = pack2(0.0f, 0.0f), gv1 = pack2(0.0f, 0.0f);
#pragma unroll
        for (int p = 0; p < 8; p++) {
            u64 tp = mul2(gp[p], fma2(f1[p], f1[p], pack2(-1.0f, -1.0f)));
            gv0 = fma2(tp, cw2[O_PW1 + v * 16 + 2 * p],     gv0);
            gv1 = fma2(tp, cw2[O_PW1 + v * 16 + 2 * p + 1], gv1);
        }
        g0 = fma2(gv0, ssp, g0);
        g1 = fma2(gv1, ssp, g1);
    }

    // ---------------- magnitude net ----------------
    u64 h[8];
#pragma unroll
    for (int o = 0; o < 8; o++) {
        u64 w0 = cw2[O_MW0 + 2 * o];
        u64 w1 = cw2[O_MW0 + 2 * o + 1];
        h[o] = elu2(fma2(w0, X0, fma2(w1, X1, cw2[O_MB0 + o])));
    }
    u64 h2[8];
#pragma unroll
    for (int o = 0; o < 8; o++)
        h2[o] = elu2(dot8c(O_MW1 + 8 * o, h, cw2[O_MB1 + o]));
    u64 bv[4];
#pragma unroll
    for (int j = 0; j < 4; j++)
        bv[j] = dot8c(O_MW2 + 8 * j, h2, cw2[O_MB2 + j]);

    const u64 m2   = fma2(bv[0], bv[1], mul2(bv[2], bv[3]));
    const u64 magA = fma2(bv[0], bv[0], mul2(bv[2], bv[2]));
    const u64 magD = fma2(bv[1], bv[1], mul2(bv[3], bv[3]));

    u64 o0 = fma2(magA, g0, mul2(m2, g1));
    u64 o1 = fma2(m2, g0, mul2(magD, g1));
    float o0l, o0h, o1l, o1h;
    unpack2(o0, o0l, o0h);
    unpack2(o1, o1l, o1h);
    reinterpret_cast<float4*>(out)[gid] = make_float4(o0l, o1l, o0h, o1h);
}

extern "C" void kernel_launch(void* const* d_in, const int* in_sizes, int n_in,
                              void* d_out, int out_size)
{
    const float* x   = (const float*)d_in[1];
    const float* mW0 = (const float*)d_in[2];
    const float* mb0 = (const float*)d_in[3];
    const float* mW1 = (const float*)d_in[4];
    const float* mb1 = (const float*)d_in[5];
    const float* mW2 = (const float*)d_in[6];
    const float* mb2 = (const float*)d_in[7];
    const float* pW1 = (const float*)d_in[8];
    const float* pb1 = (const float*)d_in[9];
    const float* pW2 = (const float*)d_in[10];
    const float* pb2 = (const float*)d_in[11];
    const float* pW3 = (const float*)d_in[12];
    const float* pb3 = (const float*)d_in[13];
    float* out = (float*)d_out;

    void* cw_ptr = nullptr;
    cudaGetSymbolAddress(&cw_ptr, cw2);

    prep_kernel<<<1, 352>>>((u64*)cw_ptr,
                            mW0, mb0, mW1, mb1, mW2, mb2,
                            pW1, pb1, pW2, pb2, pW3, pb3);

    const int nblocks = NPTS / 2 / TPB;   // 8192
    odefunc_kernel<<<nblocks, TPB>>>(x, out);
}

// round 16
// speedup vs baseline: 1.0877x; 1.0832x over previous
#include <cuda_runtime.h>

// ODEFunc_5488968204447 — R14: R9 base with PW2 rows explicitly materialized in
// the q-loop (one LDCU per weight use-pair instead of a possible double load),
// __launch_bounds__(128,5) to give the transient w[8] registers headroom.

#define NPTS 2097152
#define TPB  128

typedef unsigned long long u64;

#define O_MW0 0
#define O_MB0 16
#define O_MW1 24
#define O_MB1 88
#define O_MW2 96
#define O_MB2 128
#define O_PW1 132
#define O_PB1 164
#define O_PW2 180
#define O_PB2 308
#define O_PW3 324
#define O_PB3 340
#define SM_N  344

__constant__ u64 cw2[SM_N];          // dup-packed: element i = (w[i], w[i])

__device__ __forceinline__ u64 pack2(float lo, float hi) {
    u64 r; asm("mov.b64 %0, {%1, %2};" : "=l"(r) : "f"(lo), "f"(hi)); return r;
}
__device__ __forceinline__ void unpack2(u64 v, float& lo, float& hi) {
    asm("mov.b64 {%0, %1}, %2;" : "=f"(lo), "=f"(hi) : "l"(v));
}
__device__ __forceinline__ u64 fma2(u64 a, u64 b, u64 c) {
    u64 d; asm("fma.rn.f32x2 %0, %1, %2, %3;" : "=l"(d) : "l"(a), "l"(b), "l"(c)); return d;
}
__device__ __forceinline__ u64 mul2(u64 a, u64 b) {
    u64 d; asm("mul.rn.f32x2 %0, %1, %2;" : "=l"(d) : "l"(a), "l"(b)); return d;
}
__device__ __forceinline__ float tanhfast(float x) {
    float y; asm("tanh.approx.f32 %0, %1;" : "=f"(y) : "f"(x)); return y;
}
__device__ __forceinline__ u64 tanh2(u64 a) {
    float lo, hi; unpack2(a, lo, hi);
    return pack2(tanhfast(lo), tanhfast(hi));
}
__device__ __forceinline__ u64 elu2(u64 a) {
    float lo, hi; unpack2(a, lo, hi);
    float elo = __expf(lo) - 1.0f, ehi = __expf(hi) - 1.0f;
    lo = lo > 0.0f ? lo : elo;
    hi = hi > 0.0f ? hi : ehi;
    return pack2(lo, hi);
}

// ---------------- prep: gather -> dup-packed blob written straight into the
// constant region through its symbol address ----------------
__global__ void prep_kernel(
    u64* __restrict__ dst,
    const float* __restrict__ mW0, const float* __restrict__ mb0,
    const float* __restrict__ mW1, const float* __restrict__ mb1,
    const float* __restrict__ mW2, const float* __restrict__ mb2,
    const float* __restrict__ pW1, const float* __restrict__ pb1,
    const float* __restrict__ pW2, const float* __restrict__ pb2,
    const float* __restrict__ pW3, const float* __restrict__ pb3)
{
    int i = threadIdx.x;
    if (i >= SM_N) return;
    float v;
    if      (i < O_MB0) v = mW0[i - O_MW0];
    else if (i < O_MW1) v = mb0[i - O_MB0];
    else if (i < O_MB1) v = mW1[i - O_MW1];
    else if (i < O_MW2) v = mb1[i - O_MB1];
    else if (i < O_MB2) v = mW2[i - O_MW2];
    else if (i < O_PW1) v = mb2[i - O_MB2];
    else if (i < O_PB1) v = pW1[i - O_PW1];
    else if (i < O_PW2) v = pb1[i - O_PB1];
    else if (i < O_PB2) v = pW2[i - O_PW2];
    else if (i < O_PW3) v = pb2[i - O_PB2];
    else if (i < O_PB3) v = pW3[i - O_PW3];
    else                v = pb3[i - O_PB3];
    dst[i] = pack2(v, v);
}

// ---------------- main: 2 points per thread ----------------
__global__ __launch_bounds__(TPB, 5) void odefunc_kernel(
    const float* __restrict__ x, float* __restrict__ out)
{
    const int gid = blockIdx.x * TPB + threadIdx.x;
    float4 xv = reinterpret_cast<const float4*>(x)[gid];
    const u64 X0 = pack2(xv.x, xv.z);
    const u64 X1 = pack2(xv.y, xv.w);

    // ---------------- value nets (NV=2), fused fwd+bwd ----------------
    u64 g0 = pack2(0.0f, 0.0f), g1 = pack2(0.0f, 0.0f);
#pragma unroll
    for (int v = 0; v < 2; v++) {
        u64 f1[8];
#pragma unroll
        for (int o = 0; o < 8; o++) {
            u64 w0 = cw2[O_PW1 + v * 16 + 2 * o];
            u64 w1 = cw2[O_PW1 + v * 16 + 2 * o + 1];
            f1[o] = tanh2(fma2(w0, X0, fma2(w1, X1, cw2[O_PB1 + v * 8 + o])));
        }
        u64 z = cw2[O_PB3 + v];
        u64 gp[8];
#pragma unroll
        for (int p = 0; p < 8; p++) gp[p] = pack2(0.0f, 0.0f);
#pragma unroll
        for (int q = 0; q < 8; q++) {
            // materialize the row once: single LDCU per weight, reused by
            // both the forward dot and the gp accumulate below.
            u64 w[8];
#pragma unroll
            for (int i = 0; i < 8; i++) w[i] = cw2[O_PW2 + v * 64 + 8 * q + i];
            u64 acc = cw2[O_PB2 + v * 8 + q];
#pragma unroll
            for (int i = 0; i < 8; i++) acc = fma2(w[i], f1[i], acc);
            u64 f2  = tanh2(acc);
            u64 w3q = cw2[O_PW3 + v * 8 + q];
            z = fma2(w3q, f2, z);
            u64 gq = mul2(w3q, fma2(f2, f2, pack2(-1.0f, -1.0f)));   // w3q*(f2^2-1)
#pragma unroll
            for (int p = 0; p < 8; p++) gp[p] = fma2(gq, w[p], gp[p]);
        }
        // ss*0.5 via tanh identity: s(1-s) = 0.25*(1 - tanh^2(f3/2))
        float zl, zh; unpack2(z, zl, zh);
        float f3l = fmaf(0.5f, tanhfast(0.5f * zl), 0.5f);
        float f3h = fmaf(0.5f, tanhfast(0.5f * zh), 0.5f);
        float tl = tanhfast(0.5f * f3l);
        float th = tanhfast(0.5f * f3h);
        u64 ssp = pack2(fmaf(-0.125f * tl, tl, 0.125f),
                        fmaf(-0.125f * th, th, 0.125f));

        u64 gv0 = pack2(0.0f, 0.0f), gv1 = pack2(0.0f, 0.0f);
#pragma unroll
        for (int p = 0; p < 8; p++) {
            u64 tp = mul2(gp[p], fma2(f1[p], f1[p], pack2(-1.0f, -1.0f)));
            gv0 = fma2(tp, cw2[O_PW1 + v * 16 + 2 * p],     gv0);
            gv1 = fma2(tp, cw2[O_PW1 + v * 16 + 2 * p + 1], gv1);
        }
        g0 = fma2(gv0, ssp, g0);
        g1 = fma2(gv1, ssp, g1);
    }

    // ---------------- magnitude net ----------------
    u64 h[8];
#pragma unroll
    for (int o = 0; o < 8; o++) {
        u64 w0 = cw2[O_MW0 + 2 * o];
        u64 w1 = cw2[O_MW0 + 2 * o + 1];
        h[o] = elu2(fma2(w0, X0, fma2(w1, X1, cw2[O_MB0 + o])));
    }
    u64 h2[8];
#pragma unroll
    for (int o = 0; o < 8; o++) {
        u64 acc = cw2[O_MB1 + o];
#pragma unroll
        for (int i = 0; i < 8; i++)
            acc = fma2(cw2[O_MW1 + 8 * o + i], h[i], acc);
        h2[o] = elu2(acc);
    }
    u64 bv[4];
#pragma unroll
    for (int j = 0; j < 4; j++) {
        u64 acc = cw2[O_MB2 + j];
#pragma unroll
        for (int i = 0; i < 8; i++)
            acc = fma2(cw2[O_MW2 + 8 * j + i], h2[i], acc);
        bv[j] = acc;
    }
    const u64 m2   = fma2(bv[0], bv[1], mul2(bv[2], bv[3]));
    const u64 magA = fma2(bv[0], bv[0], mul2(bv[2], bv[2]));
    const u64 magD = fma2(bv[1], bv[1], mul2(bv[3], bv[3]));

    u64 o0 = fma2(magA, g0, mul2(m2, g1));
    u64 o1 = fma2(m2, g0, mul2(magD, g1));
    float o0l, o0h, o1l, o1h;
    unpack2(o0, o0l, o0h);
    unpack2(o1, o1l, o1h);
    reinterpret_cast<float4*>(out)[gid] = make_float4(o0l, o1l, o0h, o1h);
}

extern "C" void kernel_launch(void* const* d_in, const int* in_sizes, int n_in,
                              void* d_out, int out_size)
{
    const float* x   = (const float*)d_in[1];
    const float* mW0 = (const float*)d_in[2];
    const float* mb0 = (const float*)d_in[3];
    const float* mW1 = (const float*)d_in[4];
    const float* mb1 = (const float*)d_in[5];
    const float* mW2 = (const float*)d_in[6];
    const float* mb2 = (const float*)d_in[7];
    const float* pW1 = (const float*)d_in[8];
    const float* pb1 = (const float*)d_in[9];
    const float* pW2 = (const float*)d_in[10];
    const float* pb2 = (const float*)d_in[11];
    const float* pW3 = (const float*)d_in[12];
    const float* pb3 = (const float*)d_in[13];
    float* out = (float*)d_out;

    void* cw_ptr = nullptr;
    cudaGetSymbolAddress(&cw_ptr, cw2);

    prep_kernel<<<1, 352>>>((u64*)cw_ptr,
                            mW0, mb0, mW1, mb1, mW2, mb2,
                            pW1, pb1, pW2, pb2, pW3, pb3);

    const int nblocks = NPTS / 2 / TPB;   // 8192
    odefunc_kernel<<<nblocks, TPB>>>(x, out);
}